// round 10
// baseline (speedup 1.0000x reference)
#include <cuda_runtime.h>
#include <cuda_bf16.h>
#include <cstdint>

// Problem constants
#define BATCH 4
#define CH    256
#define NTOK  4096            // 64*64
#define GROUPS 8
#define CPG   (CH / GROUPS)   // 32
#define EPSV  1e-5f
#define SCALE 0.0625f         // CH^-0.5

// ---------------------------------------------------------------------------
// Scratch (no cudaMalloc allowed -> __device__ globals)
// ---------------------------------------------------------------------------
__device__ float g_xn [(size_t)BATCH * CH * NTOK];        // 16 MB
__device__ float g_qkv[(size_t)BATCH * 3 * CH * NTOK];    // 50 MB
__device__ float g_att[(size_t)BATCH * CH * NTOK];        // 16 MB

// ---------------------------------------------------------------------------
// helpers
// ---------------------------------------------------------------------------
__device__ __forceinline__ float tf32r(float x) {
    // round-to-nearest tf32, returned as fp32 bit pattern (low mantissa zero)
    uint32_t u;
    asm("cvt.rna.tf32.f32 %0, %1;" : "=r"(u) : "f"(x));
    return __uint_as_float(u);
}

#define MMA_TF32(d, a0, a1, a2, a3, b0, b1)                                   \
    asm volatile(                                                             \
        "mma.sync.aligned.m16n8k8.row.col.f32.tf32.tf32.f32 "                 \
        "{%0,%1,%2,%3}, {%4,%5,%6,%7}, {%8,%9}, {%0,%1,%2,%3};"               \
        : "+f"((d)[0]), "+f"((d)[1]), "+f"((d)[2]), "+f"((d)[3])              \
        : "r"(a0), "r"(a1), "r"(a2), "r"(a3), "r"(b0), "r"(b1))

__device__ __forceinline__ uint32_t fau(float f) { return __float_as_uint(f); }

// ---------------------------------------------------------------------------
// 1) GroupNorm: one CTA per (batch, group). 32 channels x 4096 = 131072 elems.
// ---------------------------------------------------------------------------
__global__ void __launch_bounds__(256) gn_kernel(
    const float* __restrict__ x, const float* __restrict__ gamma,
    const float* __restrict__ beta, float* __restrict__ xn)
{
    const int b = blockIdx.x >> 3;
    const int g = blockIdx.x & 7;
    const size_t base = ((size_t)b * CH + (size_t)g * CPG) * NTOK;
    const float* xp = x + base;
    const int CNT = CPG * NTOK;  // 131072

    float s = 0.f, ss = 0.f;
    for (int i = threadIdx.x; i < CNT; i += 256) {
        float v = xp[i];
        s += v;
        ss += v * v;
    }
#pragma unroll
    for (int off = 16; off; off >>= 1) {
        s  += __shfl_down_sync(0xffffffffu, s,  off);
        ss += __shfl_down_sync(0xffffffffu, ss, off);
    }
    __shared__ float rs[8], rss[8], stats[2];
    const int w = threadIdx.x >> 5, lane = threadIdx.x & 31;
    if (lane == 0) { rs[w] = s; rss[w] = ss; }
    __syncthreads();
    if (threadIdx.x == 0) {
        float S = 0.f, SS = 0.f;
#pragma unroll
        for (int i = 0; i < 8; i++) { S += rs[i]; SS += rss[i]; }
        float mu  = S * (1.f / (float)CNT);
        float var = SS * (1.f / (float)CNT) - mu * mu;
        stats[0] = mu;
        stats[1] = rsqrtf(var + EPSV);
    }
    __syncthreads();
    const float mu = stats[0], rstd = stats[1];
    for (int i = threadIdx.x; i < CNT; i += 256) {
        int c = g * CPG + (i >> 12);
        xn[base + i] = (xp[i] - mu) * rstd * gamma[c] + beta[c];
    }
}

// ---------------------------------------------------------------------------
// 2/4) SIMT tiled GEMM: Y[b,m,n] = sum_k W[m,k] * X[b,k,n] (+bias)(+resid)
//     64x64 tile, 256 threads, 4x4 per thread, Kd in chunks of 16.
// ---------------------------------------------------------------------------
__global__ void __launch_bounds__(256) gemm64_kernel(
    const float* __restrict__ W, const float* __restrict__ X,
    const float* __restrict__ bias, const float* __restrict__ resid,
    float* __restrict__ Y, int M, int Kd)
{
    const int Nn = NTOK;
    __shared__ __align__(16) float sA[16][68];
    __shared__ __align__(16) float sB[16][68];

    const int b = blockIdx.z;
    const float* Xb = X + (size_t)b * Kd * Nn;
    float* Yb = Y + (size_t)b * M * Nn;
    const float* Rb = resid ? resid + (size_t)b * M * Nn : nullptr;
    const int n0 = blockIdx.x * 64;
    const int m0 = blockIdx.y * 64;
    const int t  = threadIdx.x;
    const int tx = t & 15, ty = t >> 4;

    float acc[4][4] = {};

    for (int k0 = 0; k0 < Kd; k0 += 16) {
#pragma unroll
        for (int i = t; i < 1024; i += 256) {
            int mm = i >> 4, kk = i & 15;
            sA[kk][mm] = W[(size_t)(m0 + mm) * Kd + k0 + kk];
        }
#pragma unroll
        for (int i = t; i < 1024; i += 256) {
            int kk = i >> 6, nn = i & 63;
            sB[kk][nn] = Xb[(size_t)(k0 + kk) * Nn + n0 + nn];
        }
        __syncthreads();
#pragma unroll
        for (int kk = 0; kk < 16; kk++) {
            float4 av = *reinterpret_cast<const float4*>(&sA[kk][ty * 4]);
            float4 bv = *reinterpret_cast<const float4*>(&sB[kk][tx * 4]);
            float ar[4] = {av.x, av.y, av.z, av.w};
            float br[4] = {bv.x, bv.y, bv.z, bv.w};
#pragma unroll
            for (int i = 0; i < 4; i++)
#pragma unroll
                for (int j = 0; j < 4; j++) acc[i][j] += ar[i] * br[j];
        }
        __syncthreads();
    }

#pragma unroll
    for (int i = 0; i < 4; i++) {
        int m = m0 + ty * 4 + i;
        float bi = bias ? bias[m] : 0.f;
#pragma unroll
        for (int j = 0; j < 4; j++) {
            int n = n0 + tx * 4 + j;
            float v = acc[i][j] + bi;
            if (Rb) v += Rb[(size_t)m * Nn + n];
            Yb[(size_t)m * Nn + n] = v;
        }
    }
}

// ---------------------------------------------------------------------------
// 3) Fused flash attention (tf32 mma.sync), Bq=Bk=64, C=256.
//    Grid: (N/64, B). 256 threads = 8 warps.
//    Warp layout for S : 4 (q rows of 16) x 2 (k cols of 32)
//    Warp layout for PV: 4 (q rows of 16) x 2 (c halves of 128)
//    smem: Q,K,V tiles [64][260] tf32-in-f32, S/P [64][68], m/l/alpha[64]
// ---------------------------------------------------------------------------
#define QPAD 260
#define SPAD 68
#define ATTN_SMEM ((3 * 64 * QPAD + 64 * SPAD + 3 * 64) * 4)  // 217856 B

__global__ void __launch_bounds__(256, 1) attn_kernel(
    const float* __restrict__ qkv, float* __restrict__ att)
{
    extern __shared__ float sm[];
    float* sQ = sm;
    float* sK = sm + 64 * QPAD;
    float* sV = sm + 2 * 64 * QPAD;
    float* sS = sm + 3 * 64 * QPAD;
    float* sMx = sS + 64 * SPAD;
    float* sL  = sMx + 64;
    float* sAl = sL + 64;

    const int tid  = threadIdx.x;
    const int lane = tid & 31;
    const int warp = tid >> 5;
    const int wq = warp >> 1;        // 0..3 : 16-row q block
    const int wk = warp & 1;         // 0..1 : k half (S) / c half (PV)
    const int r0 = wq * 16;
    const int qr = lane >> 2;        // 0..7
    const int qc = lane & 3;         // 0..3

    const int b  = blockIdx.y;
    const int n0 = blockIdx.x * 64;
    const float* qb = qkv + (size_t)b * (3 * CH * NTOK);
    const float* kb = qb + (size_t)CH * NTOK;
    const float* vb = qb + (size_t)2 * CH * NTOK;

    if (tid < 64) { sMx[tid] = -3.0e38f; sL[tid] = 0.f; }

    // load Q tile: sQ[q][c] = q[b, c, n0+q] (tf32-rounded)
    for (int i = tid; i < 64 * CH; i += 256) {
        int c = i >> 6, j = i & 63;
        sQ[j * QPAD + c] = tf32r(qb[(size_t)c * NTOK + n0 + j]);
    }

    float o[16][4];
#pragma unroll
    for (int nt = 0; nt < 16; nt++)
#pragma unroll
        for (int j = 0; j < 4; j++) o[nt][j] = 0.f;

    __syncthreads();

    for (int kt = 0; kt < NTOK / 64; kt++) {
        const int m0 = kt * 64;
        // load K and V tiles
        for (int i = tid; i < 64 * CH; i += 256) {
            int c = i >> 6, j = i & 63;
            sK[j * QPAD + c] = tf32r(kb[(size_t)c * NTOK + m0 + j]);
            sV[j * QPAD + c] = tf32r(vb[(size_t)c * NTOK + m0 + j]);
        }
        __syncthreads();

        // ---- S = Q K^T  (16 x 32 per warp) ----
        float acc[4][4] = {};
#pragma unroll 4
        for (int kk = 0; kk < CH; kk += 8) {
            uint32_t a0 = fau(sQ[(r0 + qr) * QPAD + kk + qc]);
            uint32_t a1 = fau(sQ[(r0 + qr + 8) * QPAD + kk + qc]);
            uint32_t a2 = fau(sQ[(r0 + qr) * QPAD + kk + qc + 4]);
            uint32_t a3 = fau(sQ[(r0 + qr + 8) * QPAD + kk + qc + 4]);
#pragma unroll
            for (int nt = 0; nt < 4; nt++) {
                int col = wk * 32 + nt * 8 + qr;  // key index in tile
                uint32_t b0 = fau(sK[col * QPAD + kk + qc]);
                uint32_t b1 = fau(sK[col * QPAD + kk + qc + 4]);
                MMA_TF32(acc[nt], a0, a1, a2, a3, b0, b1);
            }
        }
        // store S * scale
#pragma unroll
        for (int nt = 0; nt < 4; nt++) {
            int row = r0 + qr;
            int col = wk * 32 + nt * 8 + 2 * qc;
            sS[row * SPAD + col]           = acc[nt][0] * SCALE;
            sS[row * SPAD + col + 1]       = acc[nt][1] * SCALE;
            sS[(row + 8) * SPAD + col]     = acc[nt][2] * SCALE;
            sS[(row + 8) * SPAD + col + 1] = acc[nt][3] * SCALE;
        }
        __syncthreads();

        // ---- online softmax: 4 lanes per row ----
        {
            int row = tid >> 2, sub = tid & 3;
            float mold = sMx[row];
            float mx = -3.0e38f;
#pragma unroll
            for (int j = sub; j < 64; j += 4) mx = fmaxf(mx, sS[row * SPAD + j]);
            mx = fmaxf(mx, __shfl_xor_sync(0xffffffffu, mx, 1));
            mx = fmaxf(mx, __shfl_xor_sync(0xffffffffu, mx, 2));
            float mnew = fmaxf(mold, mx);
            float lsum = 0.f;
#pragma unroll
            for (int j = sub; j < 64; j += 4) {
                float p = __expf(sS[row * SPAD + j] - mnew);
                sS[row * SPAD + j] = tf32r(p);
                lsum += p;
            }
            lsum += __shfl_xor_sync(0xffffffffu, lsum, 1);
            lsum += __shfl_xor_sync(0xffffffffu, lsum, 2);
            if (sub == 0) {
                float alpha = __expf(mold - mnew);
                sAl[row] = alpha;
                sMx[row] = mnew;
                sL[row]  = sL[row] * alpha + lsum;
            }
        }
        __syncthreads();

        // ---- rescale O, then O += P * V  (16 x 128 per warp) ----
        float aLo = sAl[r0 + qr];
        float aHi = sAl[r0 + qr + 8];
#pragma unroll
        for (int nt = 0; nt < 16; nt++) {
            o[nt][0] *= aLo; o[nt][1] *= aLo;
            o[nt][2] *= aHi; o[nt][3] *= aHi;
        }
#pragma unroll
        for (int kk = 0; kk < 64; kk += 8) {
            uint32_t a0 = fau(sS[(r0 + qr) * SPAD + kk + qc]);
            uint32_t a1 = fau(sS[(r0 + qr + 8) * SPAD + kk + qc]);
            uint32_t a2 = fau(sS[(r0 + qr) * SPAD + kk + qc + 4]);
            uint32_t a3 = fau(sS[(r0 + qr + 8) * SPAD + kk + qc + 4]);
#pragma unroll
            for (int nt = 0; nt < 16; nt++) {
                int col = wk * 128 + nt * 8 + qr;  // channel index
                uint32_t b0 = fau(sV[(kk + qc) * QPAD + col]);
                uint32_t b1 = fau(sV[(kk + qc + 4) * QPAD + col]);
                MMA_TF32(o[nt], a0, a1, a2, a3, b0, b1);
            }
        }
        __syncthreads();
    }

    // epilogue: divide by l, write att[b, c, n]
    const float lLo = 1.f / sL[r0 + qr];
    const float lHi = 1.f / sL[r0 + qr + 8];
    float* ab = att + (size_t)b * CH * NTOK;
    const int nLo = n0 + r0 + qr;
    const int nHi = nLo + 8;
#pragma unroll
    for (int nt = 0; nt < 16; nt++) {
        int c = wk * 128 + nt * 8 + 2 * qc;
        ab[(size_t)c * NTOK + nLo]       = o[nt][0] * lLo;
        ab[(size_t)(c + 1) * NTOK + nLo] = o[nt][1] * lLo;
        ab[(size_t)c * NTOK + nHi]       = o[nt][2] * lHi;
        ab[(size_t)(c + 1) * NTOK + nHi] = o[nt][3] * lHi;
    }
}

// ---------------------------------------------------------------------------
// launch
// ---------------------------------------------------------------------------
extern "C" void kernel_launch(void* const* d_in, const int* in_sizes, int n_in,
                              void* d_out, int out_size)
{
    const float* x      = (const float*)d_in[0];
    const float* gamma  = (const float*)d_in[1];
    const float* beta   = (const float*)d_in[2];
    const float* w_qkv  = (const float*)d_in[3];
    const float* w_proj = (const float*)d_in[4];
    const float* b_proj = (const float*)d_in[5];
    float* out = (float*)d_out;

    float *xn, *qkv, *att;
    cudaGetSymbolAddress((void**)&xn,  g_xn);
    cudaGetSymbolAddress((void**)&qkv, g_qkv);
    cudaGetSymbolAddress((void**)&att, g_att);

    // 1) GroupNorm
    gn_kernel<<<BATCH * GROUPS, 256>>>(x, gamma, beta, xn);

    // 2) QKV = W_qkv @ xn   (M=768, K=256, N=4096, batch 4)
    gemm64_kernel<<<dim3(NTOK / 64, (3 * CH) / 64, BATCH), 256>>>(
        w_qkv, xn, nullptr, nullptr, qkv, 3 * CH, CH);

    // 3) fused flash attention
    cudaFuncSetAttribute(attn_kernel,
                         cudaFuncAttributeMaxDynamicSharedMemorySize, ATTN_SMEM);
    attn_kernel<<<dim3(NTOK / 64, BATCH), 256, ATTN_SMEM>>>(qkv, att);

    // 4) out = x + W_proj @ att + b_proj
    gemm64_kernel<<<dim3(NTOK / 64, CH / 64, BATCH), 256>>>(
        w_proj, att, b_proj, x, out, CH, CH);
}

// round 11
// speedup vs baseline: 2.3579x; 2.3579x over previous
#include <cuda_runtime.h>
#include <cuda_bf16.h>
#include <cstdint>

// Problem constants
#define BATCH 4
#define CH    256
#define NTOK  4096
#define GROUPS 8
#define CPG   (CH / GROUPS)
#define EPSV  1e-5f
#define SCALE 0.0625f         // CH^-0.5

// ---------------------------------------------------------------------------
// Scratch (no cudaMalloc allowed -> __device__ globals)
// ---------------------------------------------------------------------------
__device__ float         g_xn [(size_t)BATCH * CH * NTOK];      // fp32, 16 MB
__device__ __nv_bfloat16 g_qkv[(size_t)BATCH * 3 * CH * NTOK];  // bf16, 25 MB
__device__ float         g_att[(size_t)BATCH * CH * NTOK];      // fp32, 16 MB

// ---------------------------------------------------------------------------
// helpers
// ---------------------------------------------------------------------------
__device__ __forceinline__ uint32_t prmt(uint32_t a, uint32_t b, uint32_t sel) {
    uint32_t d;
    asm("prmt.b32 %0, %1, %2, %3;" : "=r"(d) : "r"(a), "r"(b), "r"(sel));
    return d;
}

__device__ __forceinline__ void cp_async16(void* smem_dst, const void* gsrc) {
    uint32_t s = (uint32_t)__cvta_generic_to_shared(smem_dst);
    asm volatile("cp.async.cg.shared.global [%0], [%1], 16;" :: "r"(s), "l"(gsrc));
}
#define CP_COMMIT() asm volatile("cp.async.commit_group;" ::: "memory")
#define CP_WAIT0()  asm volatile("cp.async.wait_group 0;"  ::: "memory")

#define MMA_BF16(d, a0, a1, a2, a3, b0, b1)                                   \
    asm volatile(                                                             \
        "mma.sync.aligned.m16n8k16.row.col.f32.bf16.bf16.f32 "                \
        "{%0,%1,%2,%3}, {%4,%5,%6,%7}, {%8,%9}, {%0,%1,%2,%3};"               \
        : "+f"((d)[0]), "+f"((d)[1]), "+f"((d)[2]), "+f"((d)[3])              \
        : "r"(a0), "r"(a1), "r"(a2), "r"(a3), "r"(b0), "r"(b1))

// ---------------------------------------------------------------------------
// 1) GroupNorm: one CTA per (batch, group)
// ---------------------------------------------------------------------------
__global__ void __launch_bounds__(256) gn_kernel(
    const float* __restrict__ x, const float* __restrict__ gamma,
    const float* __restrict__ beta, float* __restrict__ xn)
{
    const int b = blockIdx.x >> 3;
    const int g = blockIdx.x & 7;
    const size_t base = ((size_t)b * CH + (size_t)g * CPG) * NTOK;
    const float* xp = x + base;
    const int CNT = CPG * NTOK;

    float s = 0.f, ss = 0.f;
    for (int i = threadIdx.x; i < CNT; i += 256) {
        float v = xp[i];
        s += v; ss += v * v;
    }
#pragma unroll
    for (int off = 16; off; off >>= 1) {
        s  += __shfl_down_sync(0xffffffffu, s,  off);
        ss += __shfl_down_sync(0xffffffffu, ss, off);
    }
    __shared__ float rs[8], rss[8], stats[2];
    const int w = threadIdx.x >> 5, lane = threadIdx.x & 31;
    if (lane == 0) { rs[w] = s; rss[w] = ss; }
    __syncthreads();
    if (threadIdx.x == 0) {
        float S = 0.f, SS = 0.f;
#pragma unroll
        for (int i = 0; i < 8; i++) { S += rs[i]; SS += rss[i]; }
        float mu  = S * (1.f / (float)CNT);
        float var = SS * (1.f / (float)CNT) - mu * mu;
        stats[0] = mu;
        stats[1] = rsqrtf(var + EPSV);
    }
    __syncthreads();
    const float mu = stats[0], rstd = stats[1];
    for (int i = threadIdx.x; i < CNT; i += 256) {
        int c = g * CPG + (i >> 12);
        xn[base + i] = (xp[i] - mu) * rstd * gamma[c] + beta[c];
    }
}

// ---------------------------------------------------------------------------
// 2/4) SIMT tiled GEMM: Y[b,m,n] = sum_k W[m,k]*X[b,k,n] (+bias)(+resid)
//      optional bf16 output
// ---------------------------------------------------------------------------
__global__ void __launch_bounds__(256) gemm64_kernel(
    const float* __restrict__ W, const float* __restrict__ X,
    const float* __restrict__ bias, const float* __restrict__ resid,
    void* __restrict__ Y, int M, int Kd, int out_bf16)
{
    const int Nn = NTOK;
    __shared__ __align__(16) float sA[16][68];
    __shared__ __align__(16) float sB[16][68];

    const int b = blockIdx.z;
    const float* Xb = X + (size_t)b * Kd * Nn;
    const float* Rb = resid ? resid + (size_t)b * (size_t)M * Nn : nullptr;
    const int n0 = blockIdx.x * 64;
    const int m0 = blockIdx.y * 64;
    const int t  = threadIdx.x;
    const int tx = t & 15, ty = t >> 4;

    float acc[4][4] = {};

    for (int k0 = 0; k0 < Kd; k0 += 16) {
#pragma unroll
        for (int i = t; i < 1024; i += 256) {
            int mm = i >> 4, kk = i & 15;
            sA[kk][mm] = W[(size_t)(m0 + mm) * Kd + k0 + kk];
        }
#pragma unroll
        for (int i = t; i < 1024; i += 256) {
            int kk = i >> 6, nn = i & 63;
            sB[kk][nn] = Xb[(size_t)(k0 + kk) * Nn + n0 + nn];
        }
        __syncthreads();
#pragma unroll
        for (int kk = 0; kk < 16; kk++) {
            float4 av = *reinterpret_cast<const float4*>(&sA[kk][ty * 4]);
            float4 bv = *reinterpret_cast<const float4*>(&sB[kk][tx * 4]);
            float ar[4] = {av.x, av.y, av.z, av.w};
            float br[4] = {bv.x, bv.y, bv.z, bv.w};
#pragma unroll
            for (int i = 0; i < 4; i++)
#pragma unroll
                for (int j = 0; j < 4; j++) acc[i][j] += ar[i] * br[j];
        }
        __syncthreads();
    }

    if (out_bf16) {
        __nv_bfloat16* Yb = (__nv_bfloat16*)Y + (size_t)b * (size_t)M * Nn;
#pragma unroll
        for (int i = 0; i < 4; i++) {
            int m = m0 + ty * 4 + i;
            float bi = bias ? bias[m] : 0.f;
#pragma unroll
            for (int j = 0; j < 4; j++) {
                int n = n0 + tx * 4 + j;
                Yb[(size_t)m * Nn + n] = __float2bfloat16(acc[i][j] + bi);
            }
        }
    } else {
        float* Yb = (float*)Y + (size_t)b * (size_t)M * Nn;
#pragma unroll
        for (int i = 0; i < 4; i++) {
            int m = m0 + ty * 4 + i;
            float bi = bias ? bias[m] : 0.f;
#pragma unroll
            for (int j = 0; j < 4; j++) {
                int n = n0 + tx * 4 + j;
                float v = acc[i][j] + bi;
                if (Rb) v += Rb[(size_t)m * Nn + n];
                Yb[(size_t)m * Nn + n] = v;
            }
        }
    }
}

// ---------------------------------------------------------------------------
// 3) Fused flash attention, bf16 m16n8k16 mma, double-buffered K/V.
//    Bq = Bk = 64, C = 256. Grid (N/64, B), 256 threads = 8 warps.
//
//    smem word layouts (uint32 units):
//      sQ,sK : pair layout  word(u, tok) = {x[2u][tok], x[2u+1][tok]},
//              u in [0,128), row stride TPW=72 words   (K double-buffered)
//      sV    : row copy     word(c, tw)  = {v[c][2tw], v[c][2tw+1]},
//              row stride VPW=36 words                  (double-buffered)
//      sS    : fp32 scores [64][SPW=68]
//      sP    : bf16 probs  [64] rows of PPW=36 words (72 bf16)
// ---------------------------------------------------------------------------
#define TPW 72
#define VPW 36
#define PPW 36
#define SPW 68

#define OFF_Q   0
#define OFF_K   (OFF_Q + 128 * TPW)            // 9216
#define OFF_V   (OFF_K + 2 * 128 * TPW)        // 27648
#define OFF_S   (OFF_V + 2 * 256 * VPW)        // 46080
#define OFF_P   (OFF_S + 64 * SPW)             // 50432
#define OFF_MX  (OFF_P + 64 * PPW)             // 52736
#define OFF_L   (OFF_MX + 64)
#define OFF_AL  (OFF_L + 64)
#define SMEM_WORDS (OFF_AL + 64)               // 52928
#define ATTN_SMEM (SMEM_WORDS * 4)             // 211712 B

__global__ void __launch_bounds__(256, 1) attn_kernel(
    const __nv_bfloat16* __restrict__ qkv, float* __restrict__ att)
{
    extern __shared__ uint32_t sm[];
    uint32_t* sQ = sm + OFF_Q;
    uint32_t* sK = sm + OFF_K;
    uint32_t* sV = sm + OFF_V;
    float*    sSf = (float*)(sm + OFF_S);
    uint32_t* sPw = sm + OFF_P;
    __nv_bfloat16* sPh = (__nv_bfloat16*)sPw;
    float* sMx = (float*)(sm + OFF_MX);
    float* sL  = (float*)(sm + OFF_L);
    float* sAl = (float*)(sm + OFF_AL);

    const int tid  = threadIdx.x;
    const int lane = tid & 31;
    const int warp = tid >> 5;
    const int wq = warp >> 1;   // 0..3 : 16-row q block
    const int wk = warp & 1;    // 0..1 : key half (S) / chan half (PV)
    const int r0 = wq * 16;
    const int qr = lane >> 2;   // groupID 0..7
    const int qc = lane & 3;    // threadID-in-group 0..3

    const int b  = blockIdx.y;
    const int n0 = blockIdx.x * 64;
    const uint32_t* qb32 = (const uint32_t*)(qkv + (size_t)b * 3 * CH * NTOK);
    const uint32_t* kb32 = qb32 + (size_t)CH * NTOK / 2;
    const char*     vbytes = (const char*)(kb32 + (size_t)CH * NTOK / 2);

    if (tid < 64) { sMx[tid] = -3.0e38f; sL[tid] = 0.f; }

    // ---- prologue: Q (pair layout), K tile 0, V tile 0 ----
#pragma unroll
    for (int r = 0; r < 16; r++) {
        int p = tid + 256 * r, u = p >> 5, tp = p & 31;
        uint32_t x0 = qb32[(size_t)(2 * u)     * (NTOK / 2) + (n0 >> 1) + tp];
        uint32_t x1 = qb32[(size_t)(2 * u + 1) * (NTOK / 2) + (n0 >> 1) + tp];
        *reinterpret_cast<uint2*>(sQ + u * TPW + 2 * tp) =
            make_uint2(prmt(x0, x1, 0x5410), prmt(x0, x1, 0x7632));
    }
#pragma unroll
    for (int r = 0; r < 16; r++) {
        int p = tid + 256 * r, u = p >> 5, tp = p & 31;
        uint32_t x0 = kb32[(size_t)(2 * u)     * (NTOK / 2) + tp];
        uint32_t x1 = kb32[(size_t)(2 * u + 1) * (NTOK / 2) + tp];
        *reinterpret_cast<uint2*>(sK + u * TPW + 2 * tp) =
            make_uint2(prmt(x0, x1, 0x5410), prmt(x0, x1, 0x7632));
    }
#pragma unroll
    for (int i = 0; i < 8; i++) {
        int q = tid + 256 * i, chan = q >> 3, ch = q & 7;
        cp_async16(sV + chan * VPW + ch * 4,
                   vbytes + ((size_t)chan * NTOK) * 2 + ch * 16);
    }
    CP_COMMIT();
    CP_WAIT0();
    __syncthreads();

    float o[16][4];
#pragma unroll
    for (int nt = 0; nt < 16; nt++)
#pragma unroll
        for (int j = 0; j < 4; j++) o[nt][j] = 0.f;

    for (int kt = 0; kt < NTOK / 64; kt++) {
        const int cur = kt & 1, nxt = cur ^ 1;
        const int m0n = ((kt + 1) & 63) * 64;   // next tile (wraps harmlessly)
        uint32_t* sKc = sK + cur * (128 * TPW);
        uint32_t* sKn = sK + nxt * (128 * TPW);
        uint32_t* sVc = sV + cur * (256 * VPW);
        uint32_t* sVn = sV + nxt * (256 * VPW);

        // async V prefetch for next tile
#pragma unroll
        for (int i = 0; i < 8; i++) {
            int q = tid + 256 * i, chan = q >> 3, ch = q & 7;
            cp_async16(sVn + chan * VPW + ch * 4,
                       vbytes + ((size_t)chan * NTOK + m0n) * 2 + ch * 16);
        }
        CP_COMMIT();

        // K prefetch for next tile into registers (latency hidden by S+softmax)
        uint32_t kr0[16], kr1[16];
#pragma unroll
        for (int r = 0; r < 16; r++) {
            int p = tid + 256 * r, u = p >> 5, tp = p & 31;
            kr0[r] = kb32[(size_t)(2 * u)     * (NTOK / 2) + (m0n >> 1) + tp];
            kr1[r] = kb32[(size_t)(2 * u + 1) * (NTOK / 2) + (m0n >> 1) + tp];
        }

        // ---- S = Q K^T (16 x 32 per warp) ----
        float acc[4][4] = {};
#pragma unroll
        for (int ks = 0; ks < 16; ks++) {
            const int ub = 8 * ks + qc;
            uint32_t a0 = sQ[ub * TPW + r0 + qr];
            uint32_t a1 = sQ[ub * TPW + r0 + qr + 8];
            uint32_t a2 = sQ[(ub + 4) * TPW + r0 + qr];
            uint32_t a3 = sQ[(ub + 4) * TPW + r0 + qr + 8];
#pragma unroll
            for (int nt = 0; nt < 4; nt++) {
                int col = wk * 32 + nt * 8 + qr;
                uint32_t b0 = sKc[ub * TPW + col];
                uint32_t b1 = sKc[(ub + 4) * TPW + col];
                MMA_BF16(acc[nt], a0, a1, a2, a3, b0, b1);
            }
        }
#pragma unroll
        for (int nt = 0; nt < 4; nt++) {
            int colb = wk * 32 + nt * 8 + 2 * qc;
            int rr = r0 + qr;
            sSf[rr * SPW + colb]           = acc[nt][0] * SCALE;
            sSf[rr * SPW + colb + 1]       = acc[nt][1] * SCALE;
            sSf[(rr + 8) * SPW + colb]     = acc[nt][2] * SCALE;
            sSf[(rr + 8) * SPW + colb + 1] = acc[nt][3] * SCALE;
        }
        asm volatile("bar.sync %0, 64;" :: "r"(1 + wq) : "memory");

        // ---- online softmax (pair-local): 4 lanes per row ----
        {
            int row = tid >> 2, sub = tid & 3;
            float mold = sMx[row];
            float mx = mold;
#pragma unroll
            for (int j = sub; j < 64; j += 4) mx = fmaxf(mx, sSf[row * SPW + j]);
            mx = fmaxf(mx, __shfl_xor_sync(0xffffffffu, mx, 1));
            mx = fmaxf(mx, __shfl_xor_sync(0xffffffffu, mx, 2));
            float lsum = 0.f;
#pragma unroll
            for (int j = sub; j < 64; j += 4) {
                float pv = __expf(sSf[row * SPW + j] - mx);
                sPh[row * (PPW * 2) + j] = __float2bfloat16(pv);
                lsum += pv;
            }
            lsum += __shfl_xor_sync(0xffffffffu, lsum, 1);
            lsum += __shfl_xor_sync(0xffffffffu, lsum, 2);
            if (sub == 0) {
                float alpha = __expf(mold - mx);
                sAl[row] = alpha;
                sMx[row] = mx;
                sL[row]  = sL[row] * alpha + lsum;
            }
        }
        asm volatile("bar.sync %0, 64;" :: "r"(1 + wq) : "memory");

        // ---- store K(next) : PRMT pack + STS.64, 2-wavefront pattern ----
#pragma unroll
        for (int r = 0; r < 16; r++) {
            int p = tid + 256 * r, u = p >> 5, tp = p & 31;
            *reinterpret_cast<uint2*>(sKn + u * TPW + 2 * tp) =
                make_uint2(prmt(kr0[r], kr1[r], 0x5410),
                           prmt(kr0[r], kr1[r], 0x7632));
        }

        // ---- rescale O, then O += P * V  (16 x 128 per warp) ----
        float aLo = sAl[r0 + qr];
        float aHi = sAl[r0 + qr + 8];
#pragma unroll
        for (int nt = 0; nt < 16; nt++) {
            o[nt][0] *= aLo; o[nt][1] *= aLo;
            o[nt][2] *= aHi; o[nt][3] *= aHi;
        }
#pragma unroll
        for (int ks = 0; ks < 4; ks++) {
            const int ub = 8 * ks + qc;
            uint32_t a0 = sPw[(r0 + qr) * PPW + ub];
            uint32_t a1 = sPw[(r0 + qr + 8) * PPW + ub];
            uint32_t a2 = sPw[(r0 + qr) * PPW + ub + 4];
            uint32_t a3 = sPw[(r0 + qr + 8) * PPW + ub + 4];
#pragma unroll
            for (int nt = 0; nt < 16; nt++) {
                int chan = wk * 128 + nt * 8 + qr;
                uint32_t b0 = sVc[chan * VPW + ub];
                uint32_t b1 = sVc[chan * VPW + ub + 4];
                MMA_BF16(o[nt], a0, a1, a2, a3, b0, b1);
            }
        }
        CP_WAIT0();
        __syncthreads();
    }

    // ---- epilogue: divide by l, write att[b, c, n] (fp32) ----
    const float lLo = 1.f / sL[r0 + qr];
    const float lHi = 1.f / sL[r0 + qr + 8];
    float* ab = att + (size_t)b * CH * NTOK;
    const int nLo = n0 + r0 + qr;
    const int nHi = nLo + 8;
#pragma unroll
    for (int nt = 0; nt < 16; nt++) {
        int c = wk * 128 + nt * 8 + 2 * qc;
        ab[(size_t)c * NTOK + nLo]       = o[nt][0] * lLo;
        ab[(size_t)(c + 1) * NTOK + nLo] = o[nt][1] * lLo;
        ab[(size_t)c * NTOK + nHi]       = o[nt][2] * lHi;
        ab[(size_t)(c + 1) * NTOK + nHi] = o[nt][3] * lHi;
    }
}

// ---------------------------------------------------------------------------
// launch
// ---------------------------------------------------------------------------
extern "C" void kernel_launch(void* const* d_in, const int* in_sizes, int n_in,
                              void* d_out, int out_size)
{
    const float* x      = (const float*)d_in[0];
    const float* gamma  = (const float*)d_in[1];
    const float* beta   = (const float*)d_in[2];
    const float* w_qkv  = (const float*)d_in[3];
    const float* w_proj = (const float*)d_in[4];
    const float* b_proj = (const float*)d_in[5];
    float* out = (float*)d_out;

    float *xn, *att;
    __nv_bfloat16* qkv;
    cudaGetSymbolAddress((void**)&xn,  g_xn);
    cudaGetSymbolAddress((void**)&qkv, g_qkv);
    cudaGetSymbolAddress((void**)&att, g_att);

    // 1) GroupNorm
    gn_kernel<<<BATCH * GROUPS, 256>>>(x, gamma, beta, xn);

    // 2) QKV = W_qkv @ xn  -> bf16
    gemm64_kernel<<<dim3(NTOK / 64, (3 * CH) / 64, BATCH), 256>>>(
        w_qkv, xn, nullptr, nullptr, qkv, 3 * CH, CH, 1);

    // 3) fused flash attention (bf16 mma, pipelined)
    cudaFuncSetAttribute(attn_kernel,
                         cudaFuncAttributeMaxDynamicSharedMemorySize, ATTN_SMEM);
    attn_kernel<<<dim3(NTOK / 64, BATCH), 256, ATTN_SMEM>>>(qkv, att);

    // 4) out = x + W_proj @ att + b_proj
    gemm64_kernel<<<dim3(NTOK / 64, CH / 64, BATCH), 256>>>(
        w_proj, att, b_proj, x, out, CH, CH, 0);
}